// round 8
// baseline (speedup 1.0000x reference)
#include <cuda_runtime.h>
#include <cuda_bf16.h>
#include <cstdint>

// ---------------- problem dims ----------------
#define NTOK 4096
#define EDIM 1024
#define CDIM 1024
#define HDIM 4096
#define VDIM 32000
#define LN_EPS 1e-5f

// ---- int8 GEMM tiling: BM128 BN64 Kstage64, 8 warps, warp 32x32, 2-stage, 2 CTA/SM ----
// smem stage layout (bytes): Ahi 0 (128x80), Alo 10240, Bhi 20480 (64x80), Blo 25600
#define SAHI 0u
#define SALO 10240u
#define SBHI 20480u
#define SBLO 25600u
#define STG  30720u
#define GEMM_SMEM (2 * 30720)      // 61440 B/CTA -> 2 CTA/SM

// ---------------- scratch ----------------
__device__ signed char g_wq[413138944];       // weight int8 planes (hi, lo per matrix)
__device__ signed char g_xcq[16777216];       // xc planes: hi, lo (4096x2048 each)
__device__ signed char g_h1q[33554432];       // h1 planes (4096x4096 each)
__device__ signed char g_hq [33554432];       // h planes
__device__ float g_h1f[NTOK * HDIM];
__device__ float g_hf [NTOK * HDIM];
__device__ float g_x  [NTOK * EDIM];
__device__ float g_gate[NTOK * 3072];
__device__ float g_ctx [NTOK * CDIM];
__device__ float g_gbias[2 * 3072];
__device__ float g_sB[54528];                 // per-column weight scales
__device__ float g_sA[3 * 4096];              // row scales: [xc | h1 | h]

// weight plane byte offsets; lo plane at off + sz
#define O_W00 0ull
#define Z_W00 8388608ull
#define O_W01 16777216ull
#define Z_W01 16777216ull
#define O_W10 50331648ull
#define Z_W10 8388608ull
#define O_W11 67108864ull
#define Z_W11 16777216ull
#define O_G0  100663296ull
#define Z_G   12582912ull
#define O_G1  125829120ull
#define O_OW  150994944ull
#define Z_OW  131072000ull
// sB offsets
#define S_W00 0
#define S_W01 4096
#define S_W10 8192
#define S_W11 12288
#define S_G0  16384
#define S_G1  19456
#define S_OW  22528

// ---------------- helpers ----------------
__device__ __forceinline__ uint32_t smem_u32(const void* p) {
    return (uint32_t)__cvta_generic_to_shared(p);
}
__device__ __forceinline__ void cpa16(uint32_t dst, const void* src) {
    asm volatile("cp.async.cg.shared.global [%0], [%1], 16;" :: "r"(dst), "l"(src));
}
__device__ __forceinline__ void ldm4(uint32_t* r, uint32_t a) {
    asm volatile("ldmatrix.sync.aligned.m8n8.x4.shared.b16 {%0,%1,%2,%3}, [%4];"
                 : "=r"(r[0]), "=r"(r[1]), "=r"(r[2]), "=r"(r[3]) : "r"(a));
}
__device__ __forceinline__ void mma_s8(int* d, const uint32_t* a, const uint32_t* b) {
    asm volatile("mma.sync.aligned.m16n8k32.row.col.s32.s8.s8.s32 "
                 "{%0,%1,%2,%3}, {%4,%5,%6,%7}, {%8,%9}, {%0,%1,%2,%3};"
                 : "+r"(d[0]), "+r"(d[1]), "+r"(d[2]), "+r"(d[3])
                 : "r"(a[0]), "r"(a[1]), "r"(a[2]), "r"(a[3]), "r"(b[0]), "r"(b[1]));
}
template <int ACT>
__device__ __forceinline__ float actf(float x, int col) {
    if (ACT == 1) return fmaxf(x, 0.0f);
    if (ACT == 4) return (col < 1024) ? tanhf(x) : 1.0f / (1.0f + expf(-x));
    return x;
}
// quantize 4 floats -> hi/lo packed s8 bytes
__device__ __forceinline__ void quant4(float a, float b, float c, float d, float inv,
                                       uint32_t& hB, uint32_t& lB) {
    int h[4], l[4];
    float v[4] = {a, b, c, d};
#pragma unroll
    for (int i = 0; i < 4; ++i) {
        float q  = fminf(16256.f, fmaxf(-16256.f, rintf(v[i] * inv)));
        float hf = rintf(q * (1.0f / 128.0f));
        h[i] = (int)hf;
        l[i] = (int)(q - 128.0f * hf);
    }
    hB = (h[0] & 255) | ((h[1] & 255) << 8) | ((h[2] & 255) << 16) | ((uint32_t)(h[3] & 255) << 24);
    lB = (l[0] & 255) | ((l[1] & 255) << 8) | ((l[2] & 255) << 16) | ((uint32_t)(l[3] & 255) << 24);
}

// ---------------- int8 GEMM: C[M,N] = act(dequant(Aq@Bq) + bias) ----------------
template <int ACT>
__global__ void __launch_bounds__(256, 2)
igemm(const signed char* __restrict__ Aq, const signed char* __restrict__ Bq,
      const float* __restrict__ sA, const float* __restrict__ sB,
      const float* __restrict__ bias, float* __restrict__ C,
      int M, int N, int K, int tiles_m)
{
    extern __shared__ __align__(16) char smraw[];
    const uint32_t sb0 = smem_u32(smraw);

    const int t    = threadIdx.x;
    const int lane = t & 31;
    const int warp = t >> 5;
    const int wm   = warp >> 1;       // 0..3 -> 32-row slab
    const int wn   = warp & 1;        // 0..1 -> 32-col slab
    const int bm = (blockIdx.x % tiles_m) * 128;
    const int bn = (blockIdx.x / tiles_m) * 64;
    const size_t MK = (size_t)M * K;
    const size_t NK = (size_t)N * K;

    const int ar = t >> 1, ac = (t & 1) * 32;   // A: 2 thr/row, 32 B each
    const int br = t >> 2, bc = (t & 3) * 16;   // B: 4 thr/row, 16 B each
    const signed char* aS = Aq + (size_t)(bm + ar) * K + ac;
    const signed char* bS = Bq + (size_t)(bn + br) * K + bc;
    const uint32_t daB = (uint32_t)(ar * 80 + ac);
    const uint32_t dbB = (uint32_t)(br * 80 + bc);

    int accH[2][4][4], accM[2][4][4];
#pragma unroll
    for (int a = 0; a < 2; a++)
#pragma unroll
        for (int b = 0; b < 4; b++)
#pragma unroll
            for (int c = 0; c < 4; c++) { accH[a][b][c] = 0; accM[a][b][c] = 0; }

    const int nk = K / 64;

#define ISSUE(s_)                                                        \
    do {                                                                 \
        const int s__ = (s_);                                            \
        if (s__ < nk) {                                                  \
            const uint32_t st = sb0 + (uint32_t)(s__ & 1) * STG;         \
            const signed char* pa = aS + s__ * 64;                       \
            cpa16(st + daB, pa);            cpa16(st + daB + 16, pa + 16);\
            cpa16(st + SALO + daB, pa + MK); cpa16(st + SALO + daB + 16, pa + MK + 16);\
            const signed char* pb = bS + s__ * 64;                       \
            cpa16(st + SBHI + dbB, pb);                                  \
            cpa16(st + SBLO + dbB, pb + NK);                             \
        }                                                                \
        asm volatile("cp.async.commit_group;" ::: "memory");             \
    } while (0)

    ISSUE(0); ISSUE(1);

    for (int it = 0; it < nk; ++it) {
        asm volatile("cp.async.wait_group 1;" ::: "memory");
        __syncthreads();

        const uint32_t st = sb0 + (uint32_t)(it & 1) * STG;

#pragma unroll
        for (int ks = 0; ks < 2; ++ks) {
            // B fragments: non-trans ldmatrix from [N,K] layout
            uint32_t fBh[4][2], fBl[4][2];
            const int koff = ks * 32 + ((lane & 8) << 1);
            const int nrow = (lane & 7) + ((lane & 16) >> 1);
#pragma unroll
            for (int g = 0; g < 2; ++g) {
                const uint32_t boff = (uint32_t)((wn * 32 + g * 16 + nrow) * 80 + koff);
                uint32_t r[4];
                ldm4(r, st + SBHI + boff);
                fBh[2 * g][0] = r[0]; fBh[2 * g][1] = r[1];
                fBh[2 * g + 1][0] = r[2]; fBh[2 * g + 1][1] = r[3];
                ldm4(r, st + SBLO + boff);
                fBl[2 * g][0] = r[0]; fBl[2 * g][1] = r[1];
                fBl[2 * g + 1][0] = r[2]; fBl[2 * g + 1][1] = r[3];
            }
#pragma unroll
            for (int mt = 0; mt < 2; ++mt) {
                uint32_t fAh[4], fAl[4];
                const uint32_t aoff =
                    (uint32_t)((wm * 32 + mt * 16 + (lane & 15)) * 80 +
                               ks * 32 + ((lane >> 4) << 4));
                ldm4(fAh, st + SAHI + aoff);
                ldm4(fAl, st + SALO + aoff);
#pragma unroll
                for (int nt = 0; nt < 4; ++nt) mma_s8(accH[mt][nt], fAh, fBh[nt]);
#pragma unroll
                for (int nt = 0; nt < 4; ++nt) mma_s8(accM[mt][nt], fAh, fBl[nt]);
#pragma unroll
                for (int nt = 0; nt < 4; ++nt) mma_s8(accM[mt][nt], fAl, fBh[nt]);
            }
        }
        __syncthreads();
        ISSUE(it + 2);
    }
#undef ISSUE

    // ---- epilogue: dequant + bias + act, fp32 out
    const int r0 = lane >> 2;
    const int c2 = (lane & 3) * 2;
#pragma unroll
    for (int mt = 0; mt < 2; ++mt) {
        const int row = bm + wm * 32 + mt * 16 + r0;
        const float sa0 = __ldg(sA + row);
        const float sa1 = __ldg(sA + row + 8);
        float* p0 = C + (size_t)row * N;
        float* p1 = C + (size_t)(row + 8) * N;
#pragma unroll
        for (int nt = 0; nt < 4; ++nt) {
            const int col = bn + wn * 32 + nt * 8 + c2;
            const float sb0v = __ldg(sB + col);
            const float sb1v = __ldg(sB + col + 1);
            const float b0 = __ldg(bias + col);
            const float b1 = __ldg(bias + col + 1);
            float2 o0, o1;
            o0.x = actf<ACT>(sa0 * sb0v * (16384.f * (float)accH[mt][nt][0] + 128.f * (float)accM[mt][nt][0]) + b0, col);
            o0.y = actf<ACT>(sa0 * sb1v * (16384.f * (float)accH[mt][nt][1] + 128.f * (float)accM[mt][nt][1]) + b1, col);
            o1.x = actf<ACT>(sa1 * sb0v * (16384.f * (float)accH[mt][nt][2] + 128.f * (float)accM[mt][nt][2]) + b0, col);
            o1.y = actf<ACT>(sa1 * sb1v * (16384.f * (float)accH[mt][nt][3] + 128.f * (float)accM[mt][nt][3]) + b1, col);
            *(float2*)(p0 + col) = o0;
            *(float2*)(p1 + col) = o1;
        }
    }
}

// ---------------- reductions ----------------
__device__ __forceinline__ float block_sum(float v, float* sbuf) {
    const int lane = threadIdx.x & 31;
    const int wid  = threadIdx.x >> 5;
#pragma unroll
    for (int o = 16; o; o >>= 1) v += __shfl_xor_sync(0xffffffffu, v, o);
    if (lane == 0) sbuf[wid] = v;
    __syncthreads();
    if (threadIdx.x < 32) {
        float r = (threadIdx.x < 8) ? sbuf[threadIdx.x] : 0.0f;
#pragma unroll
        for (int o = 4; o; o >>= 1) r += __shfl_xor_sync(0xffffffffu, r, o);
        if (threadIdx.x == 0) sbuf[8] = r;
    }
    __syncthreads();
    return sbuf[8];
}
__device__ __forceinline__ float block_max(float v, float* sbuf) {
    const int lane = threadIdx.x & 31;
    const int wid  = threadIdx.x >> 5;
#pragma unroll
    for (int o = 16; o; o >>= 1) v = fmaxf(v, __shfl_xor_sync(0xffffffffu, v, o));
    if (lane == 0) sbuf[wid] = v;
    __syncthreads();
    if (threadIdx.x < 32) {
        float r = (threadIdx.x < 8) ? sbuf[threadIdx.x] : 0.0f;
#pragma unroll
        for (int o = 4; o; o >>= 1) r = fmaxf(r, __shfl_xor_sync(0xffffffffu, r, o));
        if (threadIdx.x == 0) sbuf[8] = r;
    }
    __syncthreads();
    return sbuf[8];
}

// ---------------- embed + layernorm ----------------
__global__ void __launch_bounds__(256)
embed_ln_kernel(const int* __restrict__ ids, const float* __restrict__ table,
                const float* __restrict__ g, const float* __restrict__ b,
                float* __restrict__ out)
{
    __shared__ float sbuf[16];
    const int row = blockIdx.x;
    const int t = threadIdx.x;
    const float* e = table + (size_t)ids[row] * EDIM;
    float v[4];
    float s = 0.0f, s2 = 0.0f;
#pragma unroll
    for (int j = 0; j < 4; j++) {
        v[j] = e[t + j * 256];
        s += v[j]; s2 += v[j] * v[j];
    }
    const float S  = block_sum(s, sbuf);
    const float S2 = block_sum(s2, sbuf);
    const float mean = S * (1.0f / EDIM);
    const float var  = S2 * (1.0f / EDIM) - mean * mean;
    const float rs   = rsqrtf(var + LN_EPS);
#pragma unroll
    for (int j = 0; j < 4; j++) {
        const int c = t + j * 256;
        out[(size_t)row * EDIM + c] = (v[j] - mean) * rs * g[c] + b[c];
    }
}

// ---------------- concat [x|ctx] + row quant -> int8 planes ----------------
__global__ void __launch_bounds__(256)
concat_quant(const float* __restrict__ x, const float* __restrict__ ctx,
             signed char* __restrict__ dst, float* __restrict__ sAout, int first)
{
    __shared__ float sbuf[16];
    const int row = blockIdx.x;
    const int t = threadIdx.x;
    const float4 va = ((const float4*)x)[(size_t)row * 256 + t];
    const float4 vb = first ? make_float4(0.f, 0.f, 0.f, 0.f)
                            : ((const float4*)ctx)[(size_t)row * 256 + t];
    float m = fmaxf(fmaxf(fabsf(va.x), fabsf(va.y)), fmaxf(fabsf(va.z), fabsf(va.w)));
    m = fmaxf(m, fmaxf(fmaxf(fabsf(vb.x), fabsf(vb.y)), fmaxf(fabsf(vb.z), fabsf(vb.w))));
    const float amax = fmaxf(block_max(m, sbuf), 1e-20f);
    const float inv = 16256.0f / amax;
    if (t == 0) sAout[row] = amax * (1.0f / 16256.0f);
    uint32_t* hi = (uint32_t*)dst;
    uint32_t* lo = (uint32_t*)(dst + 8388608);
    uint32_t hB, lB;
    quant4(va.x, va.y, va.z, va.w, inv, hB, lB);
    hi[(size_t)row * 512 + t] = hB; lo[(size_t)row * 512 + t] = lB;
    quant4(vb.x, vb.y, vb.z, vb.w, inv, hB, lB);
    hi[(size_t)row * 512 + 256 + t] = hB; lo[(size_t)row * 512 + 256 + t] = lB;
}

// ---------------- activation row quant (K = 4096) ----------------
__global__ void __launch_bounds__(256)
actquant(const float* __restrict__ src, signed char* __restrict__ dstH,
         signed char* __restrict__ dstL, float* __restrict__ sAout)
{
    __shared__ float sbuf[16];
    const int row = blockIdx.x;
    const int t = threadIdx.x;
    const float4* s4 = (const float4*)(src + (size_t)row * HDIM);
    float4 v[4];
    float m = 0.0f;
#pragma unroll
    for (int j = 0; j < 4; j++) {
        v[j] = s4[t + j * 256];
        m = fmaxf(m, fmaxf(fmaxf(fabsf(v[j].x), fabsf(v[j].y)),
                           fmaxf(fabsf(v[j].z), fabsf(v[j].w))));
    }
    const float amax = fmaxf(block_max(m, sbuf), 1e-20f);
    const float inv = 16256.0f / amax;
    if (t == 0) sAout[row] = amax * (1.0f / 16256.0f);
    uint32_t* hi = (uint32_t*)dstH;
    uint32_t* lo = (uint32_t*)dstL;
#pragma unroll
    for (int j = 0; j < 4; j++) {
        uint32_t hB, lB;
        quant4(v[j].x, v[j].y, v[j].z, v[j].w, inv, hB, lB);
        hi[(size_t)row * 1024 + t + j * 256] = hB;
        lo[(size_t)row * 1024 + t + j * 256] = lB;
    }
}

// ---------------- weight column amax ----------------
__global__ void __launch_bounds__(256)
colmax(const float* __restrict__ src, float* __restrict__ sBout, int K, int N)
{
    const int n = blockIdx.x * 256 + threadIdx.x;
    if (n >= N) return;
    float m = 0.0f;
    for (int k = 0; k < K; ++k) m = fmaxf(m, fabsf(src[(size_t)k * N + n]));
    sBout[n] = fmaxf(m, 1e-20f) * (1.0f / 16256.0f);
}

// ---------------- weight transpose-pack [K,N] f32 -> [N,K] s8 planes ----------------
// block (32,8); grid (K/128, N/32). FUSED: compute column scales in-kernel (w00 only).
template <int FUSED>
__global__ void __launch_bounds__(256)
packw(const float* __restrict__ src, signed char* __restrict__ dstH,
      signed char* __restrict__ dstL, float* __restrict__ sBv, int K, int N)
{
    __shared__ float tile[128][33];
    __shared__ float red[8][33];
    __shared__ float sc[32];
    const int tx = threadIdx.x, ty = threadIdx.y;
    const int k0 = blockIdx.x * 128;
    const int n0 = blockIdx.y * 32;

    if (FUSED) {
        float m = 0.0f;
        for (int k = ty; k < K; k += 8) m = fmaxf(m, fabsf(src[(size_t)k * N + n0 + tx]));
        red[ty][tx] = m;
        __syncthreads();
        if (ty == 0) {
            float mm = red[0][tx];
#pragma unroll
            for (int j = 1; j < 8; ++j) mm = fmaxf(mm, red[j][tx]);
            const float s = fmaxf(mm, 1e-20f) * (1.0f / 16256.0f);
            sc[tx] = 1.0f / s;
            if (blockIdx.x == 0) sBv[n0 + tx] = s;
        }
        __syncthreads();
    }
    for (int r = ty; r < 128; r += 8)
        tile[r][tx] = src[(size_t)(k0 + r) * N + n0 + tx];
    __syncthreads();

    for (int nn = ty; nn < 32; nn += 8) {
        const int n = n0 + nn;
        const float inv = FUSED ? sc[nn] : (1.0f / __ldg(sBv + n));
        uint32_t hB, lB;
        quant4(tile[tx * 4 + 0][nn], tile[tx * 4 + 1][nn],
               tile[tx * 4 + 2][nn], tile[tx * 4 + 3][nn], inv, hB, lB);
        ((uint32_t*)(dstH + (size_t)n * K))[k0 / 4 + tx] = hB;
        ((uint32_t*)(dstL + (size_t)n * K))[k0 / 4 + tx] = lB;
    }
}

__global__ void __launch_bounds__(256)
gbias_kernel(const float* __restrict__ db, const float* __restrict__ fb,
             const float* __restrict__ ib, float* __restrict__ out)
{
    const int c = blockIdx.x * 256 + threadIdx.x;
    if (c >= 3072) return;
    out[c] = (c < 1024) ? db[c] : (c < 2048 ? fb[c - 1024] : ib[c - 2048]);
}

// gates layout: [delta | f | i] per row of 3072
__global__ void __launch_bounds__(256)
gate_ln_kernel(const float* __restrict__ gates, float* __restrict__ ctx,
               const float* __restrict__ g, const float* __restrict__ b, int first)
{
    __shared__ float sbuf[16];
    const int row = blockIdx.x;
    const int t = threadIdx.x;
    const float* gr = gates + (size_t)row * 3072;
    float v[4];
    float s = 0.0f, s2 = 0.0f;
#pragma unroll
    for (int j = 0; j < 4; j++) {
        const int c = t + j * 256;
        const float cv = first ? 0.0f : ctx[(size_t)row * CDIM + c];
        v[j] = gr[1024 + c] * cv + gr[2048 + c] * gr[c];
        s += v[j]; s2 += v[j] * v[j];
    }
    const float S  = block_sum(s, sbuf);
    const float S2 = block_sum(s2, sbuf);
    const float mean = S * (1.0f / CDIM);
    const float var  = S2 * (1.0f / CDIM) - mean * mean;
    const float rs   = rsqrtf(var + LN_EPS);
#pragma unroll
    for (int j = 0; j < 4; j++) {
        const int c = t + j * 256;
        ctx[(size_t)row * CDIM + c] = (v[j] - mean) * rs * g[c] + b[c];
    }
}

// ---------------- host dispatch ----------------
static void run_igemm(int act, const signed char* Aq, const signed char* Bq,
                      const float* sA, const float* sB, const float* bias,
                      float* C, int M, int N, int K)
{
    const int tiles_m = M / 128;
    dim3 grid(tiles_m * (N / 64)), block(256);
    if (act == 1) {
        cudaFuncSetAttribute(igemm<1>, cudaFuncAttributeMaxDynamicSharedMemorySize, GEMM_SMEM);
        igemm<1><<<grid, block, GEMM_SMEM>>>(Aq, Bq, sA, sB, bias, C, M, N, K, tiles_m);
    } else if (act == 4) {
        cudaFuncSetAttribute(igemm<4>, cudaFuncAttributeMaxDynamicSharedMemorySize, GEMM_SMEM);
        igemm<4><<<grid, block, GEMM_SMEM>>>(Aq, Bq, sA, sB, bias, C, M, N, K, tiles_m);
    } else {
        cudaFuncSetAttribute(igemm<0>, cudaFuncAttributeMaxDynamicSharedMemorySize, GEMM_SMEM);
        igemm<0><<<grid, block, GEMM_SMEM>>>(Aq, Bq, sA, sB, bias, C, M, N, K, tiles_m);
    }
}

extern "C" void kernel_launch(void* const* d_in, const int* in_sizes, int n_in,
                              void* d_out, int out_size)
{
    const int*   ids   = (const int*)d_in[0];
    const float* table = (const float*)d_in[1];
    const float* en_g  = (const float*)d_in[2];
    const float* en_b  = (const float*)d_in[3];
    const float* bA[2] = {(const float*)d_in[5],  (const float*)d_in[9]};
    const float* bB[2] = {(const float*)d_in[7],  (const float*)d_in[11]};
    const float* cg[2] = {(const float*)d_in[18], (const float*)d_in[26]};
    const float* cb[2] = {(const float*)d_in[19], (const float*)d_in[27]};
    const float* ob    = (const float*)d_in[29];
    float* out = (float*)d_out;

    signed char *wq, *xcq, *h1q, *hq;
    float *h1f, *hf, *x, *gate, *ctx, *gbias, *sB, *sA;
    cudaGetSymbolAddress((void**)&wq,   g_wq);
    cudaGetSymbolAddress((void**)&xcq,  g_xcq);
    cudaGetSymbolAddress((void**)&h1q,  g_h1q);
    cudaGetSymbolAddress((void**)&hq,   g_hq);
    cudaGetSymbolAddress((void**)&h1f,  g_h1f);
    cudaGetSymbolAddress((void**)&hf,   g_hf);
    cudaGetSymbolAddress((void**)&x,    g_x);
    cudaGetSymbolAddress((void**)&gate, g_gate);
    cudaGetSymbolAddress((void**)&ctx,  g_ctx);
    cudaGetSymbolAddress((void**)&gbias,g_gbias);
    cudaGetSymbolAddress((void**)&sB,   g_sB);
    cudaGetSymbolAddress((void**)&sA,   g_sA);

    float* sAxc = sA;
    float* sAh1 = sA + 4096;
    float* sAh  = sA + 8192;

    const dim3 pb(32, 8);
    #define PACK2(W, KK, NN, OFF, SZ, SOFF)                                           \
        do {                                                                          \
            colmax<<<((NN) + 255) / 256, 256>>>((const float*)(W), sB + (SOFF), (KK), (NN)); \
            packw<0><<<dim3((KK) / 128, (NN) / 32), pb>>>((const float*)(W),          \
                wq + (OFF), wq + (OFF) + (SZ), sB + (SOFF), (KK), (NN));              \
        } while (0)

    // 0: embed, 1: concat_quant, 2: fused pack w00, 3: trunk GEMM 1 (profiled)
    embed_ln_kernel<<<NTOK, 256>>>(ids, table, en_g, en_b, x);
    concat_quant<<<NTOK, 256>>>(x, ctx, xcq, sAxc, 1);
    packw<1><<<dim3(2048 / 128, 4096 / 32), pb>>>((const float*)d_in[4],
        wq + O_W00, wq + O_W00 + Z_W00, sB + S_W00, 2048, 4096);
    run_igemm(1, xcq, wq + O_W00, sAxc, sB + S_W00, bA[0], h1f, NTOK, HDIM, 2048);
    actquant<<<NTOK, 256>>>(h1f, h1q, h1q + 16777216, sAh1);
    PACK2(d_in[6], 4096, 4096, O_W01, Z_W01, S_W01);
    run_igemm(1, h1q, wq + O_W01, sAh1, sB + S_W01, bB[0], hf, NTOK, HDIM, HDIM);
    actquant<<<NTOK, 256>>>(hf, hq, hq + 16777216, sAh);
    gbias_kernel<<<12, 256>>>((const float*)d_in[13], (const float*)d_in[15],
                              (const float*)d_in[17], gbias);
    gbias_kernel<<<12, 256>>>((const float*)d_in[21], (const float*)d_in[23],
                              (const float*)d_in[25], gbias + 3072);
    // gates block 0: dw0|fw0|iw0 -> G0 planes at col offsets 0/1024/2048
    colmax<<<4, 256>>>((const float*)d_in[12], sB + S_G0, 4096, 1024);
    packw<0><<<dim3(32, 32), pb>>>((const float*)d_in[12], wq + O_G0,
        wq + O_G0 + Z_G, sB + S_G0, 4096, 1024);
    colmax<<<4, 256>>>((const float*)d_in[14], sB + S_G0 + 1024, 4096, 1024);
    packw<0><<<dim3(32, 32), pb>>>((const float*)d_in[14], wq + O_G0 + 1024ull * 4096,
        wq + O_G0 + Z_G + 1024ull * 4096, sB + S_G0 + 1024, 4096, 1024);
    colmax<<<4, 256>>>((const float*)d_in[16], sB + S_G0 + 2048, 4096, 1024);
    packw<0><<<dim3(32, 32), pb>>>((const float*)d_in[16], wq + O_G0 + 2048ull * 4096,
        wq + O_G0 + Z_G + 2048ull * 4096, sB + S_G0 + 2048, 4096, 1024);
    run_igemm(4, hq, wq + O_G0, sAh, sB + S_G0, gbias, gate, NTOK, 3072, HDIM);
    gate_ln_kernel<<<NTOK, 256>>>(gate, ctx, cg[0], cb[0], 1);

    // ---- block 1
    concat_quant<<<NTOK, 256>>>(x, ctx, xcq, sAxc, 0);
    PACK2(d_in[8], 2048, 4096, O_W10, Z_W10, S_W10);
    run_igemm(1, xcq, wq + O_W10, sAxc, sB + S_W10, bA[1], h1f, NTOK, HDIM, 2048);
    actquant<<<NTOK, 256>>>(h1f, h1q, h1q + 16777216, sAh1);
    PACK2(d_in[10], 4096, 4096, O_W11, Z_W11, S_W11);
    run_igemm(1, h1q, wq + O_W11, sAh1, sB + S_W11, bB[1], hf, NTOK, HDIM, HDIM);
    actquant<<<NTOK, 256>>>(hf, hq, hq + 16777216, sAh);
    colmax<<<4, 256>>>((const float*)d_in[20], sB + S_G1, 4096, 1024);
    packw<0><<<dim3(32, 32), pb>>>((const float*)d_in[20], wq + O_G1,
        wq + O_G1 + Z_G, sB + S_G1, 4096, 1024);
    colmax<<<4, 256>>>((const float*)d_in[22], sB + S_G1 + 1024, 4096, 1024);
    packw<0><<<dim3(32, 32), pb>>>((const float*)d_in[22], wq + O_G1 + 1024ull * 4096,
        wq + O_G1 + Z_G + 1024ull * 4096, sB + S_G1 + 1024, 4096, 1024);
    colmax<<<4, 256>>>((const float*)d_in[24], sB + S_G1 + 2048, 4096, 1024);
    packw<0><<<dim3(32, 32), pb>>>((const float*)d_in[24], wq + O_G1 + 2048ull * 4096,
        wq + O_G1 + Z_G + 2048ull * 4096, sB + S_G1 + 2048, 4096, 1024);
    run_igemm(4, hq, wq + O_G1, sAh, sB + S_G1, gbias + 3072, gate, NTOK, 3072, HDIM);
    gate_ln_kernel<<<NTOK, 256>>>(gate, ctx, cg[1], cb[1], 0);

    // ---- logits
    PACK2(d_in[28], 4096, 32000, O_OW, Z_OW, S_OW);
    run_igemm(0, hq, wq + O_OW, sAh, sB + S_OW, ob, out, NTOK, VDIM, HDIM);
    #undef PACK2
}

// round 9
// speedup vs baseline: 3.7356x; 3.7356x over previous
#include <cuda_runtime.h>
#include <cuda_fp16.h>
#include <cstdint>

// ---------------- problem dims ----------------
#define NTOK 4096
#define EDIM 1024
#define CDIM 1024
#define HDIM 4096
#define VDIM 32000
#define LN_EPS 1e-5f

// ---- fp16 2-term GEMM tiling: BM128 BN128 BK32, 8 warps, warp 64x32, 2-stage, 2 CTA/SM ----
#define LDA 40
#define LDB 136
#define APB (128 * LDA * 2)          // 10240 B per A plane (hi or lo)
#define BPB (32 * LDB * 2)           // 8704 B  (B hi plane only)
#define SBOF (2 * APB)               // 20480
#define STG (2 * APB + BPB)          // 29184 B per stage
#define GEMM_SMEM (2 * STG)          // 58368 B -> two CTAs per SM

// ---------------- scratch ----------------
__device__ __half g_wbuf[206569472];              // fp16 weight planes (single plane each)
__device__ __half g_xcs[2 * 4096 * 2048];         // concat: hi plane, lo plane
__device__ __half g_h1s[2 * 4096 * 4096];
__device__ __half g_hs [2 * 4096 * 4096];
__device__ float g_x   [NTOK * EDIM];
__device__ float g_gate[NTOK * 3072];             // [delta | f | i]
__device__ float g_ctx [NTOK * CDIM];
__device__ float g_gbias[2 * 3072];

// weight plane offsets in __half elements
#define O_W00 0ull
#define O_W01 8388608ull
#define O_W10 25165824ull
#define O_W11 33554432ull
#define O_G0  50331648ull
#define O_G1  62914560ull
#define O_OW  75497472ull

// ---------------- helpers ----------------
__device__ __forceinline__ uint32_t smem_u32(const void* p) {
    return (uint32_t)__cvta_generic_to_shared(p);
}
__device__ __forceinline__ void cpa16(uint32_t dst, const void* src) {
    asm volatile("cp.async.cg.shared.global [%0], [%1], 16;" :: "r"(dst), "l"(src));
}
__device__ __forceinline__ void ldm4(uint32_t* r, uint32_t a) {
    asm volatile("ldmatrix.sync.aligned.m8n8.x4.shared.b16 {%0,%1,%2,%3}, [%4];"
                 : "=r"(r[0]), "=r"(r[1]), "=r"(r[2]), "=r"(r[3]) : "r"(a));
}
__device__ __forceinline__ void ldmT4(uint32_t* r, uint32_t a) {
    asm volatile("ldmatrix.sync.aligned.m8n8.x4.trans.shared.b16 {%0,%1,%2,%3}, [%4];"
                 : "=r"(r[0]), "=r"(r[1]), "=r"(r[2]), "=r"(r[3]) : "r"(a));
}
__device__ __forceinline__ void mma_f16(float* d, const uint32_t* a, const uint32_t* b) {
    asm volatile("mma.sync.aligned.m16n8k16.row.col.f32.f16.f16.f32 "
                 "{%0,%1,%2,%3}, {%4,%5,%6,%7}, {%8,%9}, {%0,%1,%2,%3};"
                 : "+f"(d[0]), "+f"(d[1]), "+f"(d[2]), "+f"(d[3])
                 : "r"(a[0]), "r"(a[1]), "r"(a[2]), "r"(a[3]), "r"(b[0]), "r"(b[1]));
}
// split fp32 pair into fp16 hi pair + fp16 residual pair (packed)
__device__ __forceinline__ void cvt2h(float x, float y, uint32_t& hi, uint32_t& lo) {
    __half2 h = __floats2half2_rn(x, y);
    float rx = x - __low2float(h);
    float ry = y - __high2float(h);
    __half2 l = __floats2half2_rn(rx, ry);
    hi = *reinterpret_cast<uint32_t*>(&h);
    lo = *reinterpret_cast<uint32_t*>(&l);
}
// fp32 pair -> packed fp16 pair
__device__ __forceinline__ uint32_t cvth(float x, float y) {
    __half2 h = __floats2half2_rn(x, y);
    return *reinterpret_cast<uint32_t*>(&h);
}
template <int ACT>
__device__ __forceinline__ float actf(float x, int col) {
    if (ACT == 1) return fmaxf(x, 0.0f);
    if (ACT == 4) return (col < 1024) ? tanhf(x) : 1.0f / (1.0f + expf(-x));
    return x;
}

// ---------------- GEMM: C[M,N] = act(A @ fp16(B) + bias) ----------------
// A: fp16 hi plane at Ah, lo plane at Ah + M*K. B: single fp16 plane [K,N].
template <int ACT, int SPLIT_OUT>
__global__ void __launch_bounds__(256, 2)
hgemm(const __half* __restrict__ Ah,
      const __half* __restrict__ Bh,
      const float* __restrict__ bias,
      float* __restrict__ Cf, __half* __restrict__ Cs,
      int M, int N, int K, int tiles_m)
{
    extern __shared__ __align__(16) char smraw[];
    const uint32_t sb0 = smem_u32(smraw);

    const int t    = threadIdx.x;
    const int lane = t & 31;
    const int warp = t >> 5;
    const int wm   = warp >> 2;
    const int wn   = warp & 3;
    const int bm = (blockIdx.x % tiles_m) * 128;
    const int bn = (blockIdx.x / tiles_m) * 128;
    const size_t MK = (size_t)M * K;

    const int ar  = t >> 1;
    const int acH = (t & 1) * 16;
    const int br  = t >> 3;
    const int bcH = (t & 7) * 16;
    const __half* aS = Ah + (size_t)(bm + ar) * K + acH;
    const __half* bS = Bh + (size_t)br * N + bn + bcH;
    const uint32_t daB = (uint32_t)(ar * LDA + acH) * 2;
    const uint32_t dbB = (uint32_t)(br * LDB + bcH) * 2;

    float acc[4][4][4];
#pragma unroll
    for (int a = 0; a < 4; a++)
#pragma unroll
        for (int b = 0; b < 4; b++)
#pragma unroll
            for (int c = 0; c < 4; c++) acc[a][b][c] = 0.0f;

    const int nk = K / 32;

#define ISSUE(s_)                                                       \
    do {                                                                \
        const int s__ = (s_);                                           \
        if (s__ < nk) {                                                 \
            const uint32_t st = sb0 + (uint32_t)(s__ & 1) * STG;        \
            const __half* pa = aS + s__ * 32;                           \
            const uint32_t da = st + daB;                               \
            cpa16(da, pa);            cpa16(da + 16, pa + 8);           \
            cpa16(da + APB, pa + MK); cpa16(da + APB + 16, pa + MK + 8);\
            const __half* pb = bS + (size_t)(s__ * 32) * N;             \
            const uint32_t db = st + SBOF + dbB;                        \
            cpa16(db, pb);            cpa16(db + 16, pb + 8);           \
        }                                                               \
        asm volatile("cp.async.commit_group;" ::: "memory");            \
    } while (0)

    ISSUE(0); ISSUE(1);

    for (int it = 0; it < nk; ++it) {
        asm volatile("cp.async.wait_group 1;" ::: "memory");
        __syncthreads();

        const uint32_t st  = sb0 + (uint32_t)(it & 1) * STG;
        const uint32_t aHi = st;
        const uint32_t aLo = st + APB;
        const uint32_t bPl = st + SBOF;

#pragma unroll
        for (int ks = 0; ks < 2; ++ks) {
            uint32_t fB[4][2];
            const int krow  = ks * 16 + (lane & 15);
            const int nbase = wn * 32 + ((lane >> 4) << 3);
#pragma unroll
            for (int g = 0; g < 2; ++g) {
                const uint32_t off = (uint32_t)(krow * LDB + nbase + g * 16) * 2;
                uint32_t r[4];
                ldmT4(r, bPl + off);
                fB[2 * g][0] = r[0]; fB[2 * g][1] = r[1];
                fB[2 * g + 1][0] = r[2]; fB[2 * g + 1][1] = r[3];
            }
#pragma unroll
            for (int mt = 0; mt < 4; ++mt) {
                uint32_t fH[4], fL[4];
                const uint32_t aoff =
                    (uint32_t)((wm * 64 + mt * 16 + (lane & 15)) * LDA +
                               ks * 16 + ((lane >> 4) << 3)) * 2;
                ldm4(fH, aHi + aoff);
                ldm4(fL, aLo + aoff);
#pragma unroll
                for (int nt = 0; nt < 4; ++nt) mma_f16(acc[mt][nt], fH, fB[nt]);
#pragma unroll
                for (int nt = 0; nt < 4; ++nt) mma_f16(acc[mt][nt], fL, fB[nt]);
            }
        }
        __syncthreads();
        ISSUE(it + 2);
    }
#undef ISSUE

    // ---- epilogue
    const int rr = lane >> 2;
    const int cc = (lane & 3) * 2;
    if (SPLIT_OUT) {
        uint32_t* Chi = (uint32_t*)Cs;
        uint32_t* Clo = (uint32_t*)(Cs + (size_t)M * N);
#pragma unroll
        for (int mt = 0; mt < 4; ++mt) {
            const int row = bm + wm * 64 + mt * 16 + rr;
#pragma unroll
            for (int nt = 0; nt < 4; ++nt) {
                const int col = bn + wn * 32 + nt * 8 + cc;
                const float b0 = __ldg(bias + col);
                const float b1 = __ldg(bias + col + 1);
                uint32_t h, l;
                cvt2h(actf<ACT>(acc[mt][nt][0] + b0, col),
                      actf<ACT>(acc[mt][nt][1] + b1, col), h, l);
                size_t ix = ((size_t)row * N + col) >> 1;
                Chi[ix] = h; Clo[ix] = l;
                cvt2h(actf<ACT>(acc[mt][nt][2] + b0, col),
                      actf<ACT>(acc[mt][nt][3] + b1, col), h, l);
                ix = ((size_t)(row + 8) * N + col) >> 1;
                Chi[ix] = h; Clo[ix] = l;
            }
        }
    } else {
#pragma unroll
        for (int mt = 0; mt < 4; ++mt) {
            const int row = bm + wm * 64 + mt * 16 + rr;
#pragma unroll
            for (int nt = 0; nt < 4; ++nt) {
                const int col = bn + wn * 32 + nt * 8 + cc;
                const float b0 = __ldg(bias + col);
                const float b1 = __ldg(bias + col + 1);
                float2 o0, o1;
                o0.x = actf<ACT>(acc[mt][nt][0] + b0, col);
                o0.y = actf<ACT>(acc[mt][nt][1] + b1, col);
                o1.x = actf<ACT>(acc[mt][nt][2] + b0, col);
                o1.y = actf<ACT>(acc[mt][nt][3] + b1, col);
                *(float2*)(Cf + (size_t)row * N + col)       = o0;
                *(float2*)(Cf + (size_t)(row + 8) * N + col) = o1;
            }
        }
    }
}

// ---------------- weight convert fp32 -> single fp16 plane ----------------
// global float2 index space (103284736 total); gates interleaved [dw|fw|iw] -> N=3072
__device__ __forceinline__ void conv_one(
    long long i,
    const float* w00, const float* w01, const float* w10, const float* w11,
    const float* dw0, const float* fw0, const float* iw0,
    const float* dw1, const float* fw1, const float* iw1,
    const float* ow, __half* wbuf)
{
    const float* s; long long jsrc;
    if (i < 4194304LL)        { s = w00; jsrc = i; }
    else if (i < 12582912LL)  { s = w01; jsrc = i - 4194304; }
    else if (i < 16777216LL)  { s = w10; jsrc = i - 12582912; }
    else if (i < 25165824LL)  { s = w11; jsrc = i - 16777216; }
    else if (i < 31457280LL) {
        const long long j = i - 25165824;
        const long long r = j / 1536, c2 = j % 1536;
        const int sel = (int)(c2 / 512);
        s = sel == 0 ? dw0 : (sel == 1 ? fw0 : iw0);
        jsrc = r * 512 + (c2 - (long long)sel * 512);
    }
    else if (i < 37748736LL) {
        const long long j = i - 31457280;
        const long long r = j / 1536, c2 = j % 1536;
        const int sel = (int)(c2 / 512);
        s = sel == 0 ? dw1 : (sel == 1 ? fw1 : iw1);
        jsrc = r * 512 + (c2 - (long long)sel * 512);
    }
    else { s = ow; jsrc = i - 37748736; }

    const float2 v = ((const float2*)s)[jsrc];
    ((uint32_t*)wbuf)[i] = cvth(v.x, v.y);
}

__global__ void __launch_bounds__(256)
wconv_range(const float* w00, const float* w01, const float* w10, const float* w11,
            const float* dw0, const float* fw0, const float* iw0,
            const float* dw1, const float* fw1, const float* iw1,
            const float* ow, __half* wbuf, long long base, long long count)
{
    const long long i = base + (long long)blockIdx.x * 256 + threadIdx.x;
    if (i >= base + count || i >= 103284736LL) return;
    conv_one(i, w00, w01, w10, w11, dw0, fw0, iw0, dw1, fw1, iw1, ow, wbuf);
}

__global__ void __launch_bounds__(256)
gbias_kernel(const float* __restrict__ db, const float* __restrict__ fb,
             const float* __restrict__ ib, float* __restrict__ out)
{
    const int c = blockIdx.x * 256 + threadIdx.x;
    if (c >= 3072) return;
    out[c] = (c < 1024) ? db[c] : (c < 2048 ? fb[c - 1024] : ib[c - 2048]);
}

// ---------------- concat [x | ctx] -> fp16 hi/lo planes ----------------
__global__ void __launch_bounds__(256)
concat_split_kernel(const float* __restrict__ x, const float* __restrict__ ctx,
                    __half* __restrict__ xcs, int first)
{
    const int gid = blockIdx.x * 256 + threadIdx.x;   // float4 over [4096,2048]
    const int row = gid >> 9;
    const int c4  = gid & 511;
    float4 v;
    if (c4 < 256)   v = ((const float4*)x)[row * 256 + c4];
    else if (first) v = make_float4(0.f, 0.f, 0.f, 0.f);
    else            v = ((const float4*)ctx)[row * 256 + (c4 - 256)];
    uint32_t h0, l0, h1, l1;
    cvt2h(v.x, v.y, h0, l0);
    cvt2h(v.z, v.w, h1, l1);
    uint2* hi = (uint2*)xcs;
    uint2* lo = (uint2*)(xcs + (size_t)4096 * 2048);
    hi[gid] = make_uint2(h0, h1);
    lo[gid] = make_uint2(l0, l1);
}

// ---------------- block reduction ----------------
__device__ __forceinline__ float block_sum(float v, float* sbuf) {
    const int lane = threadIdx.x & 31;
    const int wid  = threadIdx.x >> 5;
#pragma unroll
    for (int o = 16; o; o >>= 1) v += __shfl_xor_sync(0xffffffffu, v, o);
    if (lane == 0) sbuf[wid] = v;
    __syncthreads();
    if (threadIdx.x < 32) {
        float r = (threadIdx.x < 8) ? sbuf[threadIdx.x] : 0.0f;
#pragma unroll
        for (int o = 4; o; o >>= 1) r += __shfl_xor_sync(0xffffffffu, r, o);
        if (threadIdx.x == 0) sbuf[8] = r;
    }
    __syncthreads();
    return sbuf[8];
}

__global__ void __launch_bounds__(256)
embed_ln_kernel(const int* __restrict__ ids, const float* __restrict__ table,
                const float* __restrict__ g, const float* __restrict__ b,
                float* __restrict__ out)
{
    __shared__ float sbuf[16];
    const int row = blockIdx.x;
    const int t = threadIdx.x;
    const float* e = table + (size_t)ids[row] * EDIM;
    float v[4];
    float s = 0.0f, s2 = 0.0f;
#pragma unroll
    for (int j = 0; j < 4; j++) {
        v[j] = e[t + j * 256];
        s += v[j]; s2 += v[j] * v[j];
    }
    const float S  = block_sum(s, sbuf);
    const float S2 = block_sum(s2, sbuf);
    const float mean = S * (1.0f / EDIM);
    const float var  = S2 * (1.0f / EDIM) - mean * mean;
    const float rs   = rsqrtf(var + LN_EPS);
#pragma unroll
    for (int j = 0; j < 4; j++) {
        const int c = t + j * 256;
        out[(size_t)row * EDIM + c] = (v[j] - mean) * rs * g[c] + b[c];
    }
}

// gates layout: [delta | f | i] per row of 3072
__global__ void __launch_bounds__(256)
gate_ln_kernel(const float* __restrict__ gates, float* __restrict__ ctx,
               const float* __restrict__ g, const float* __restrict__ b, int first)
{
    __shared__ float sbuf[16];
    const int row = blockIdx.x;
    const int t = threadIdx.x;
    const float* gr = gates + (size_t)row * 3072;
    float v[4];
    float s = 0.0f, s2 = 0.0f;
#pragma unroll
    for (int j = 0; j < 4; j++) {
        const int c = t + j * 256;
        const float cv = first ? 0.0f : ctx[(size_t)row * CDIM + c];
        v[j] = gr[1024 + c] * cv + gr[2048 + c] * gr[c];
        s += v[j]; s2 += v[j] * v[j];
    }
    const float S  = block_sum(s, sbuf);
    const float S2 = block_sum(s2, sbuf);
    const float mean = S * (1.0f / CDIM);
    const float var  = S2 * (1.0f / CDIM) - mean * mean;
    const float rs   = rsqrtf(var + LN_EPS);
#pragma unroll
    for (int j = 0; j < 4; j++) {
        const int c = t + j * 256;
        ctx[(size_t)row * CDIM + c] = (v[j] - mean) * rs * g[c] + b[c];
    }
}

// ---------------- host dispatch ----------------
static void run_gemm(int mode, const __half* Ah, const __half* Bh,
                     const float* bias, float* Cf, __half* Cs,
                     int M, int N, int K)
{
    const int tiles_m = M / 128;
    dim3 grid(tiles_m * (N / 128)), block(256);
    if (mode == 0) {            // trunk: relu + split fp16 out
        cudaFuncSetAttribute(hgemm<1, 1>, cudaFuncAttributeMaxDynamicSharedMemorySize, GEMM_SMEM);
        hgemm<1, 1><<<grid, block, GEMM_SMEM>>>(Ah, Bh, bias, Cf, Cs, M, N, K, tiles_m);
    } else if (mode == 1) {     // gates: mixed tanh/sigmoid, fp32 out
        cudaFuncSetAttribute(hgemm<4, 0>, cudaFuncAttributeMaxDynamicSharedMemorySize, GEMM_SMEM);
        hgemm<4, 0><<<grid, block, GEMM_SMEM>>>(Ah, Bh, bias, Cf, Cs, M, N, K, tiles_m);
    } else {                    // logits: none, fp32 out
        cudaFuncSetAttribute(hgemm<0, 0>, cudaFuncAttributeMaxDynamicSharedMemorySize, GEMM_SMEM);
        hgemm<0, 0><<<grid, block, GEMM_SMEM>>>(Ah, Bh, bias, Cf, Cs, M, N, K, tiles_m);
    }
}

extern "C" void kernel_launch(void* const* d_in, const int* in_sizes, int n_in,
                              void* d_out, int out_size)
{
    const int*   ids   = (const int*)d_in[0];
    const float* table = (const float*)d_in[1];
    const float* en_g  = (const float*)d_in[2];
    const float* en_b  = (const float*)d_in[3];
    const float* bA[2] = {(const float*)d_in[5],  (const float*)d_in[9]};
    const float* bB[2] = {(const float*)d_in[7],  (const float*)d_in[11]};
    const float* cg[2] = {(const float*)d_in[18], (const float*)d_in[26]};
    const float* cb[2] = {(const float*)d_in[19], (const float*)d_in[27]};
    const float* ob    = (const float*)d_in[29];
    float* out = (float*)d_out;

    __half *wbuf, *xcs, *h1s, *hs;
    float *x, *gate, *ctx, *gbias;
    cudaGetSymbolAddress((void**)&wbuf,  g_wbuf);
    cudaGetSymbolAddress((void**)&xcs,   g_xcs);
    cudaGetSymbolAddress((void**)&h1s,   g_h1s);
    cudaGetSymbolAddress((void**)&hs,    g_hs);
    cudaGetSymbolAddress((void**)&x,     g_x);
    cudaGetSymbolAddress((void**)&gate,  g_gate);
    cudaGetSymbolAddress((void**)&ctx,   g_ctx);
    cudaGetSymbolAddress((void**)&gbias, g_gbias);

    const float* W[11] = {
        (const float*)d_in[4],  (const float*)d_in[6],
        (const float*)d_in[8],  (const float*)d_in[10],
        (const float*)d_in[12], (const float*)d_in[14], (const float*)d_in[16],
        (const float*)d_in[20], (const float*)d_in[22], (const float*)d_in[24],
        (const float*)d_in[28]};

    // 0: embed, 1: concat(blk0), 2: conv w00, 3: trunk GEMM 1 (profiled),
    // 4: conv rest, 5: trunk GEMM 2, ...
    embed_ln_kernel<<<NTOK, 256>>>(ids, table, en_g, en_b, x);
    concat_split_kernel<<<(NTOK * 2048 / 4) / 256, 256>>>(x, ctx, xcs, 1);
    wconv_range<<<(4194304 + 255) / 256, 256>>>(
        W[0], W[1], W[2], W[3], W[4], W[5], W[6], W[7], W[8], W[9], W[10],
        wbuf, 0LL, 4194304LL);
    run_gemm(0, xcs, wbuf + O_W00, bA[0], nullptr, h1s, NTOK, HDIM, EDIM + CDIM);
    wconv_range<<<(int)((103284736LL - 4194304LL + 255) / 256), 256>>>(
        W[0], W[1], W[2], W[3], W[4], W[5], W[6], W[7], W[8], W[9], W[10],
        wbuf, 4194304LL, 103284736LL - 4194304LL);
    run_gemm(0, h1s, wbuf + O_W01, bB[0], nullptr, hs, NTOK, HDIM, HDIM);
    gbias_kernel<<<12, 256>>>((const float*)d_in[13], (const float*)d_in[15],
                              (const float*)d_in[17], gbias);
    gbias_kernel<<<12, 256>>>((const float*)d_in[21], (const float*)d_in[23],
                              (const float*)d_in[25], gbias + 3072);
    run_gemm(1, hs, wbuf + O_G0, gbias, gate, nullptr, NTOK, 3072, HDIM);
    gate_ln_kernel<<<NTOK, 256>>>(gate, ctx, cg[0], cb[0], 1);

    // block 1
    concat_split_kernel<<<(NTOK * 2048 / 4) / 256, 256>>>(x, ctx, xcs, 0);
    run_gemm(0, xcs, wbuf + O_W10, bA[1], nullptr, h1s, NTOK, HDIM, EDIM + CDIM);
    run_gemm(0, h1s, wbuf + O_W11, bB[1], nullptr, hs,  NTOK, HDIM, HDIM);
    run_gemm(1, hs,  wbuf + O_G1, gbias + 3072, gate, nullptr, NTOK, 3072, HDIM);
    gate_ln_kernel<<<NTOK, 256>>>(gate, ctx, cg[1], cb[1], 0);

    run_gemm(2, hs, wbuf + O_OW, ob, out, nullptr, NTOK, VDIM, HDIM);
}

// round 10
// speedup vs baseline: 5.6923x; 1.5238x over previous
#include <cuda_runtime.h>
#include <cuda_fp16.h>
#include <cstdint>

// ---------------- problem dims ----------------
#define NTOK 4096
#define EDIM 1024
#define CDIM 1024
#define HDIM 4096
#define VDIM 32000
#define LN_EPS 1e-5f

// ---- fp16 GEMM tiling: BM128 BN128 BK32, 8 warps, warp 64x32, 2-stage, 2 CTA/SM ----
#define LDA 40
#define LDB 136
#define APB (128 * LDA * 2)          // 10240 B per A plane (hi or lo)
#define BPB (32 * LDB * 2)           // 8704 B  (B plane)
#define SBOF (2 * APB)               // 20480
#define STG (2 * APB + BPB)          // 29184 B per stage
#define GEMM_SMEM (2 * STG)          // 58368 B -> two CTAs per SM

// ---------------- scratch ----------------
__device__ __half g_wbuf[206569472];              // fp16 weight planes
__device__ __half g_xcs[2 * 4096 * 2048];         // concat: hi plane, lo plane
__device__ __half g_h1s[2 * 4096 * 4096];
__device__ __half g_hs [2 * 4096 * 4096];
__device__ float g_x   [NTOK * EDIM];
__device__ float g_gate[NTOK * 3072];             // [delta | f | i]
__device__ float g_ctx [NTOK * CDIM];
__device__ float g_gbias[3072];

// weight plane offsets in __half elements
#define O_W00 0ull
#define O_W01 8388608ull
#define O_W10 25165824ull
#define O_W11 33554432ull
#define O_G0  50331648ull
#define O_G1  62914560ull
#define O_OW  75497472ull

// ---------------- helpers ----------------
__device__ __forceinline__ uint32_t smem_u32(const void* p) {
    return (uint32_t)__cvta_generic_to_shared(p);
}
__device__ __forceinline__ void cpa16(uint32_t dst, const void* src) {
    asm volatile("cp.async.cg.shared.global [%0], [%1], 16;" :: "r"(dst), "l"(src));
}
__device__ __forceinline__ void ldm4(uint32_t* r, uint32_t a) {
    asm volatile("ldmatrix.sync.aligned.m8n8.x4.shared.b16 {%0,%1,%2,%3}, [%4];"
                 : "=r"(r[0]), "=r"(r[1]), "=r"(r[2]), "=r"(r[3]) : "r"(a));
}
__device__ __forceinline__ void ldmT4(uint32_t* r, uint32_t a) {
    asm volatile("ldmatrix.sync.aligned.m8n8.x4.trans.shared.b16 {%0,%1,%2,%3}, [%4];"
                 : "=r"(r[0]), "=r"(r[1]), "=r"(r[2]), "=r"(r[3]) : "r"(a));
}
__device__ __forceinline__ void mma_f16(float* d, const uint32_t* a, const uint32_t* b) {
    asm volatile("mma.sync.aligned.m16n8k16.row.col.f32.f16.f16.f32 "
                 "{%0,%1,%2,%3}, {%4,%5,%6,%7}, {%8,%9}, {%0,%1,%2,%3};"
                 : "+f"(d[0]), "+f"(d[1]), "+f"(d[2]), "+f"(d[3])
                 : "r"(a[0]), "r"(a[1]), "r"(a[2]), "r"(a[3]), "r"(b[0]), "r"(b[1]));
}
// split fp32 pair into fp16 hi pair + fp16 residual pair (packed)
__device__ __forceinline__ void cvt2h(float x, float y, uint32_t& hi, uint32_t& lo) {
    __half2 h = __floats2half2_rn(x, y);
    float rx = x - __low2float(h);
    float ry = y - __high2float(h);
    __half2 l = __floats2half2_rn(rx, ry);
    hi = *reinterpret_cast<uint32_t*>(&h);
    lo = *reinterpret_cast<uint32_t*>(&l);
}
__device__ __forceinline__ uint32_t cvth(float x, float y) {
    __half2 h = __floats2half2_rn(x, y);
    return *reinterpret_cast<uint32_t*>(&h);
}
template <int ACT>
__device__ __forceinline__ float actf(float x, int col) {
    if (ACT == 1) return fmaxf(x, 0.0f);
    if (ACT == 4) return (col < 1024) ? tanhf(x) : 1.0f / (1.0f + expf(-x));
    return x;
}

// ---------------- GEMM: C[M,N] = act(A @ fp16(B) + bias) ----------------
// A: fp16 hi plane at Ah (+ lo plane at Ah + M*K when TERMS==2). B: fp16 [K,N].
template <int ACT, int SPLIT_OUT, int TERMS>
__global__ void __launch_bounds__(256, 2)
hgemm(const __half* __restrict__ Ah,
      const __half* __restrict__ Bh,
      const float* __restrict__ bias,
      float* __restrict__ Cf, __half* __restrict__ Cs,
      int M, int N, int K, int tiles_m)
{
    extern __shared__ __align__(16) char smraw[];
    const uint32_t sb0 = smem_u32(smraw);

    const int t    = threadIdx.x;
    const int lane = t & 31;
    const int warp = t >> 5;
    const int wm   = warp >> 2;
    const int wn   = warp & 3;
    const int bm = (blockIdx.x % tiles_m) * 128;
    const int bn = (blockIdx.x / tiles_m) * 128;
    const size_t MK = (size_t)M * K;

    const int ar  = t >> 1;
    const int acH = (t & 1) * 16;
    const int br  = t >> 3;
    const int bcH = (t & 7) * 16;
    const __half* aS = Ah + (size_t)(bm + ar) * K + acH;
    const __half* bS = Bh + (size_t)br * N + bn + bcH;
    const uint32_t daB = (uint32_t)(ar * LDA + acH) * 2;
    const uint32_t dbB = (uint32_t)(br * LDB + bcH) * 2;

    float acc[4][4][4];
#pragma unroll
    for (int a = 0; a < 4; a++)
#pragma unroll
        for (int b = 0; b < 4; b++)
#pragma unroll
            for (int c = 0; c < 4; c++) acc[a][b][c] = 0.0f;

    const int nk = K / 32;

#define ISSUE(s_)                                                       \
    do {                                                                \
        const int s__ = (s_);                                           \
        if (s__ < nk) {                                                 \
            const uint32_t st = sb0 + (uint32_t)(s__ & 1) * STG;        \
            const __half* pa = aS + s__ * 32;                           \
            const uint32_t da = st + daB;                               \
            cpa16(da, pa);            cpa16(da + 16, pa + 8);           \
            if (TERMS == 2) {                                           \
                cpa16(da + APB, pa + MK);                               \
                cpa16(da + APB + 16, pa + MK + 8);                      \
            }                                                           \
            const __half* pb = bS + (size_t)(s__ * 32) * N;             \
            const uint32_t db = st + SBOF + dbB;                        \
            cpa16(db, pb);            cpa16(db + 16, pb + 8);           \
        }                                                               \
        asm volatile("cp.async.commit_group;" ::: "memory");            \
    } while (0)

    ISSUE(0); ISSUE(1);

    for (int it = 0; it < nk; ++it) {
        asm volatile("cp.async.wait_group 1;" ::: "memory");
        __syncthreads();

        const uint32_t st  = sb0 + (uint32_t)(it & 1) * STG;
        const uint32_t aHi = st;
        const uint32_t aLo = st + APB;
        const uint32_t bPl = st + SBOF;

#pragma unroll
        for (int ks = 0; ks < 2; ++ks) {
            uint32_t fB[4][2];
            const int krow  = ks * 16 + (lane & 15);
            const int nbase = wn * 32 + ((lane >> 4) << 3);
#pragma unroll
            for (int g = 0; g < 2; ++g) {
                const uint32_t off = (uint32_t)(krow * LDB + nbase + g * 16) * 2;
                uint32_t r[4];
                ldmT4(r, bPl + off);
                fB[2 * g][0] = r[0]; fB[2 * g][1] = r[1];
                fB[2 * g + 1][0] = r[2]; fB[2 * g + 1][1] = r[3];
            }
#pragma unroll
            for (int mt = 0; mt < 4; ++mt) {
                uint32_t fH[4], fL[4];
                const uint32_t aoff =
                    (uint32_t)((wm * 64 + mt * 16 + (lane & 15)) * LDA +
                               ks * 16 + ((lane >> 4) << 3)) * 2;
                ldm4(fH, aHi + aoff);
                if (TERMS == 2) ldm4(fL, aLo + aoff);
#pragma unroll
                for (int nt = 0; nt < 4; ++nt) mma_f16(acc[mt][nt], fH, fB[nt]);
                if (TERMS == 2) {
#pragma unroll
                    for (int nt = 0; nt < 4; ++nt) mma_f16(acc[mt][nt], fL, fB[nt]);
                }
            }
        }
        __syncthreads();
        ISSUE(it + 2);
    }
#undef ISSUE

    // ---- epilogue
    const int rr = lane >> 2;
    const int cc = (lane & 3) * 2;
    if (SPLIT_OUT) {
        uint32_t* Chi = (uint32_t*)Cs;
        uint32_t* Clo = (uint32_t*)(Cs + (size_t)M * N);
#pragma unroll
        for (int mt = 0; mt < 4; ++mt) {
            const int row = bm + wm * 64 + mt * 16 + rr;
#pragma unroll
            for (int nt = 0; nt < 4; ++nt) {
                const int col = bn + wn * 32 + nt * 8 + cc;
                const float b0 = __ldg(bias + col);
                const float b1 = __ldg(bias + col + 1);
                uint32_t h, l;
                cvt2h(actf<ACT>(acc[mt][nt][0] + b0, col),
                      actf<ACT>(acc[mt][nt][1] + b1, col), h, l);
                size_t ix = ((size_t)row * N + col) >> 1;
                Chi[ix] = h; Clo[ix] = l;
                cvt2h(actf<ACT>(acc[mt][nt][2] + b0, col),
                      actf<ACT>(acc[mt][nt][3] + b1, col), h, l);
                ix = ((size_t)(row + 8) * N + col) >> 1;
                Chi[ix] = h; Clo[ix] = l;
            }
        }
    } else {
#pragma unroll
        for (int mt = 0; mt < 4; ++mt) {
            const int row = bm + wm * 64 + mt * 16 + rr;
#pragma unroll
            for (int nt = 0; nt < 4; ++nt) {
                const int col = bn + wn * 32 + nt * 8 + cc;
                const float b0 = __ldg(bias + col);
                const float b1 = __ldg(bias + col + 1);
                float2 o0, o1;
                o0.x = actf<ACT>(acc[mt][nt][0] + b0, col);
                o0.y = actf<ACT>(acc[mt][nt][1] + b1, col);
                o1.x = actf<ACT>(acc[mt][nt][2] + b0, col);
                o1.y = actf<ACT>(acc[mt][nt][3] + b1, col);
                *(float2*)(Cf + (size_t)row * N + col)       = o0;
                *(float2*)(Cf + (size_t)(row + 8) * N + col) = o1;
            }
        }
    }
}

// ---------------- weight convert fp32 -> fp16 plane ----------------
__device__ __forceinline__ void conv_one(
    long long i,
    const float* w00, const float* w01, const float* w10, const float* w11,
    const float* dw0, const float* fw0, const float* iw0,
    const float* ow, __half* wbuf)
{
    const float* s; long long jsrc; long long dsti = i;
    if (i < 4194304LL)        { s = w00; jsrc = i; }
    else if (i < 12582912LL)  { s = w01; jsrc = i - 4194304; }
    else if (i < 16777216LL)  { s = w10; jsrc = i - 12582912; }
    else if (i < 25165824LL)  { s = w11; jsrc = i - 16777216; }
    else if (i < 31457280LL) {
        const long long j = i - 25165824;
        const long long r = j / 1536, c2 = j % 1536;
        const int sel = (int)(c2 / 512);
        s = sel == 0 ? dw0 : (sel == 1 ? fw0 : iw0);
        jsrc = r * 512 + (c2 - (long long)sel * 512);
    }
    else { s = ow; jsrc = i - 31457280; dsti = i + 6291456; }  // skip unused G1 slot

    const float2 v = ((const float2*)s)[jsrc];
    ((uint32_t*)wbuf)[dsti] = cvth(v.x, v.y);
}

__global__ void __launch_bounds__(256)
wconv_range(const float* w00, const float* w01, const float* w10, const float* w11,
            const float* dw0, const float* fw0, const float* iw0,
            const float* ow, __half* wbuf, long long base, long long count)
{
    const long long i = base + (long long)blockIdx.x * 256 + threadIdx.x;
    if (i >= base + count || i >= 96993280LL) return;
    conv_one(i, w00, w01, w10, w11, dw0, fw0, iw0, ow, wbuf);
}

__global__ void __launch_bounds__(256)
gbias_kernel(const float* __restrict__ db, const float* __restrict__ fb,
             const float* __restrict__ ib, float* __restrict__ out)
{
    const int c = blockIdx.x * 256 + threadIdx.x;
    if (c >= 3072) return;
    out[c] = (c < 1024) ? db[c] : (c < 2048 ? fb[c - 1024] : ib[c - 2048]);
}

// ---------------- concat [x | ctx] -> fp16 hi/lo planes ----------------
__global__ void __launch_bounds__(256)
concat_split_kernel(const float* __restrict__ x, const float* __restrict__ ctx,
                    __half* __restrict__ xcs, int first)
{
    const int gid = blockIdx.x * 256 + threadIdx.x;
    const int row = gid >> 9;
    const int c4  = gid & 511;
    float4 v;
    if (c4 < 256)   v = ((const float4*)x)[row * 256 + c4];
    else if (first) v = make_float4(0.f, 0.f, 0.f, 0.f);
    else            v = ((const float4*)ctx)[row * 256 + (c4 - 256)];
    uint32_t h0, l0, h1, l1;
    cvt2h(v.x, v.y, h0, l0);
    cvt2h(v.z, v.w, h1, l1);
    uint2* hi = (uint2*)xcs;
    uint2* lo = (uint2*)(xcs + (size_t)4096 * 2048);
    hi[gid] = make_uint2(h0, h1);
    lo[gid] = make_uint2(l0, l1);
}

// ---------------- block reduction ----------------
__device__ __forceinline__ float block_sum(float v, float* sbuf) {
    const int lane = threadIdx.x & 31;
    const int wid  = threadIdx.x >> 5;
#pragma unroll
    for (int o = 16; o; o >>= 1) v += __shfl_xor_sync(0xffffffffu, v, o);
    if (lane == 0) sbuf[wid] = v;
    __syncthreads();
    if (threadIdx.x < 32) {
        float r = (threadIdx.x < 8) ? sbuf[threadIdx.x] : 0.0f;
#pragma unroll
        for (int o = 4; o; o >>= 1) r += __shfl_xor_sync(0xffffffffu, r, o);
        if (threadIdx.x == 0) sbuf[8] = r;
    }
    __syncthreads();
    return sbuf[8];
}

__global__ void __launch_bounds__(256)
embed_ln_kernel(const int* __restrict__ ids, const float* __restrict__ table,
                const float* __restrict__ g, const float* __restrict__ b,
                float* __restrict__ out)
{
    __shared__ float sbuf[16];
    const int row = blockIdx.x;
    const int t = threadIdx.x;
    const float* e = table + (size_t)ids[row] * EDIM;
    float v[4];
    float s = 0.0f, s2 = 0.0f;
#pragma unroll
    for (int j = 0; j < 4; j++) {
        v[j] = e[t + j * 256];
        s += v[j]; s2 += v[j] * v[j];
    }
    const float S  = block_sum(s, sbuf);
    const float S2 = block_sum(s2, sbuf);
    const float mean = S * (1.0f / EDIM);
    const float var  = S2 * (1.0f / EDIM) - mean * mean;
    const float rs   = rsqrtf(var + LN_EPS);
#pragma unroll
    for (int j = 0; j < 4; j++) {
        const int c = t + j * 256;
        out[(size_t)row * EDIM + c] = (v[j] - mean) * rs * g[c] + b[c];
    }
}

// gates layout: [delta | f | i] per row of 3072
__global__ void __launch_bounds__(256)
gate_ln_kernel(const float* __restrict__ gates, float* __restrict__ ctx,
               const float* __restrict__ g, const float* __restrict__ b, int first)
{
    __shared__ float sbuf[16];
    const int row = blockIdx.x;
    const int t = threadIdx.x;
    const float* gr = gates + (size_t)row * 3072;
    float v[4];
    float s = 0.0f, s2 = 0.0f;
#pragma unroll
    for (int j = 0; j < 4; j++) {
        const int c = t + j * 256;
        const float cv = first ? 0.0f : ctx[(size_t)row * CDIM + c];
        v[j] = gr[1024 + c] * cv + gr[2048 + c] * gr[c];
        s += v[j]; s2 += v[j] * v[j];
    }
    const float S  = block_sum(s, sbuf);
    const float S2 = block_sum(s2, sbuf);
    const float mean = S * (1.0f / CDIM);
    const float var  = S2 * (1.0f / CDIM) - mean * mean;
    const float rs   = rsqrtf(var + LN_EPS);
#pragma unroll
    for (int j = 0; j < 4; j++) {
        const int c = t + j * 256;
        ctx[(size_t)row * CDIM + c] = (v[j] - mean) * rs * g[c] + b[c];
    }
}

// ---------------- host dispatch ----------------
static void run_gemm(int mode, const __half* Ah, const __half* Bh,
                     const float* bias, float* Cf, __half* Cs,
                     int M, int N, int K)
{
    const int tiles_m = M / 128;
    dim3 grid(tiles_m * (N / 128)), block(256);
    if (mode == 0) {            // trunk: relu + split fp16 out, 2-term
        cudaFuncSetAttribute(hgemm<1, 1, 2>, cudaFuncAttributeMaxDynamicSharedMemorySize, GEMM_SMEM);
        hgemm<1, 1, 2><<<grid, block, GEMM_SMEM>>>(Ah, Bh, bias, Cf, Cs, M, N, K, tiles_m);
    } else if (mode == 1) {     // gates: mixed tanh/sigmoid, fp32 out, 2-term
        cudaFuncSetAttribute(hgemm<4, 0, 2>, cudaFuncAttributeMaxDynamicSharedMemorySize, GEMM_SMEM);
        hgemm<4, 0, 2><<<grid, block, GEMM_SMEM>>>(Ah, Bh, bias, Cf, Cs, M, N, K, tiles_m);
    } else {                    // logits: none, fp32 out, 1-term
        cudaFuncSetAttribute(hgemm<0, 0, 1>, cudaFuncAttributeMaxDynamicSharedMemorySize, GEMM_SMEM);
        hgemm<0, 0, 1><<<grid, block, GEMM_SMEM>>>(Ah, Bh, bias, Cf, Cs, M, N, K, tiles_m);
    }
}

extern "C" void kernel_launch(void* const* d_in, const int* in_sizes, int n_in,
                              void* d_out, int out_size)
{
    const int*   ids   = (const int*)d_in[0];
    const float* table = (const float*)d_in[1];
    const float* en_g  = (const float*)d_in[2];
    const float* en_b  = (const float*)d_in[3];
    const float* bA[2] = {(const float*)d_in[5],  (const float*)d_in[9]};
    const float* bB[2] = {(const float*)d_in[7],  (const float*)d_in[11]};
    const float* cg0   = (const float*)d_in[18];
    const float* cb0   = (const float*)d_in[19];
    const float* ob    = (const float*)d_in[29];
    float* out = (float*)d_out;

    __half *wbuf, *xcs, *h1s, *hs;
    float *x, *gate, *ctx, *gbias;
    cudaGetSymbolAddress((void**)&wbuf,  g_wbuf);
    cudaGetSymbolAddress((void**)&xcs,   g_xcs);
    cudaGetSymbolAddress((void**)&h1s,   g_h1s);
    cudaGetSymbolAddress((void**)&hs,    g_hs);
    cudaGetSymbolAddress((void**)&x,     g_x);
    cudaGetSymbolAddress((void**)&gate,  g_gate);
    cudaGetSymbolAddress((void**)&ctx,   g_ctx);
    cudaGetSymbolAddress((void**)&gbias, g_gbias);

    const float* W[8] = {
        (const float*)d_in[4],  (const float*)d_in[6],
        (const float*)d_in[8],  (const float*)d_in[10],
        (const float*)d_in[12], (const float*)d_in[14], (const float*)d_in[16],
        (const float*)d_in[28]};

    // 0: embed, 1: concat(blk0), 2: conv w00, 3: trunk GEMM 1 (profiled),
    // 4: conv rest, 5: trunk GEMM 2, ...
    embed_ln_kernel<<<NTOK, 256>>>(ids, table, en_g, en_b, x);
    concat_split_kernel<<<(NTOK * 2048 / 4) / 256, 256>>>(x, ctx, xcs, 1);
    wconv_range<<<(4194304 + 255) / 256, 256>>>(
        W[0], W[1], W[2], W[3], W[4], W[5], W[6], W[7],
        wbuf, 0LL, 4194304LL);
    run_gemm(0, xcs, wbuf + O_W00, bA[0], nullptr, h1s, NTOK, HDIM, EDIM + CDIM);
    wconv_range<<<(int)((96993280LL - 4194304LL + 255) / 256), 256>>>(
        W[0], W[1], W[2], W[3], W[4], W[5], W[6], W[7],
        wbuf, 4194304LL, 96993280LL - 4194304LL);
    run_gemm(0, h1s, wbuf + O_W01, bB[0], nullptr, hs, NTOK, HDIM, HDIM);
    gbias_kernel<<<12, 256>>>((const float*)d_in[13], (const float*)d_in[15],
                              (const float*)d_in[17], gbias);
    run_gemm(1, hs, wbuf + O_G0, gbias, gate, nullptr, NTOK, 3072, HDIM);
    gate_ln_kernel<<<NTOK, 256>>>(gate, ctx, cg0, cb0, 1);

    // block 1 (gate GEMM + gate_ln are dead code: final ctx never read)
    concat_split_kernel<<<(NTOK * 2048 / 4) / 256, 256>>>(x, ctx, xcs, 0);
    run_gemm(0, xcs, wbuf + O_W10, bA[1], nullptr, h1s, NTOK, HDIM, EDIM + CDIM);
    run_gemm(0, h1s, wbuf + O_W11, bB[1], nullptr, hs,  NTOK, HDIM, HDIM);

    // logits: 1-term fp16 (error un-amplified at the output layer)
    run_gemm(2, hs, wbuf + O_OW, ob, out, nullptr, NTOK, VDIM, HDIM);
}

// round 11
// speedup vs baseline: 6.5583x; 1.1521x over previous
#include <cuda_runtime.h>
#include <cuda_fp16.h>
#include <cstdint>

// ---------------- problem dims ----------------
#define NTOK 4096
#define EDIM 1024
#define CDIM 1024
#define HDIM 4096
#define VDIM 32000
#define LN_EPS 1e-5f

// ---- fp16 GEMM tiling: BM128 BN128 BK32, 8 warps, warp 64x32, 2-stage, 2 CTA/SM ----
#define LDA 40
#define LDB 136
#define APB (128 * LDA * 2)          // 10240 B per A plane (hi or lo)
#define BPB (32 * LDB * 2)           // 8704 B  (B plane)
#define SBOF (2 * APB)               // 20480
#define STG (2 * APB + BPB)          // 29184 B per stage
#define GEMM_SMEM (2 * STG)          // 58368 B -> two CTAs per SM

// ---------------- scratch ----------------
__device__ __half g_wbuf[206569472];              // fp16 weight planes
__device__ __half g_xcs[2 * 4096 * 2048];         // concat: hi plane, lo plane
__device__ __half g_h1s[2 * 4096 * 4096];
__device__ __half g_hs [2 * 4096 * 4096];
__device__ float g_x   [NTOK * EDIM];
__device__ float g_gate[NTOK * 3072];             // [delta | f | i]
__device__ float g_ctx [NTOK * CDIM];
__device__ float g_gbias[3072];

// weight plane offsets in __half elements
#define O_W00 0ull
#define O_W01 8388608ull
#define O_W10 25165824ull
#define O_W11 33554432ull
#define O_G0  50331648ull
#define O_OW  75497472ull

// ---------------- helpers ----------------
__device__ __forceinline__ uint32_t smem_u32(const void* p) {
    return (uint32_t)__cvta_generic_to_shared(p);
}
__device__ __forceinline__ void cpa16(uint32_t dst, const void* src) {
    asm volatile("cp.async.cg.shared.global [%0], [%1], 16;" :: "r"(dst), "l"(src));
}
__device__ __forceinline__ void ldm4(uint32_t* r, uint32_t a) {
    asm volatile("ldmatrix.sync.aligned.m8n8.x4.shared.b16 {%0,%1,%2,%3}, [%4];"
                 : "=r"(r[0]), "=r"(r[1]), "=r"(r[2]), "=r"(r[3]) : "r"(a));
}
__device__ __forceinline__ void ldmT4(uint32_t* r, uint32_t a) {
    asm volatile("ldmatrix.sync.aligned.m8n8.x4.trans.shared.b16 {%0,%1,%2,%3}, [%4];"
                 : "=r"(r[0]), "=r"(r[1]), "=r"(r[2]), "=r"(r[3]) : "r"(a));
}
__device__ __forceinline__ void mma_f16(float* d, const uint32_t* a, const uint32_t* b) {
    asm volatile("mma.sync.aligned.m16n8k16.row.col.f32.f16.f16.f32 "
                 "{%0,%1,%2,%3}, {%4,%5,%6,%7}, {%8,%9}, {%0,%1,%2,%3};"
                 : "+f"(d[0]), "+f"(d[1]), "+f"(d[2]), "+f"(d[3])
                 : "r"(a[0]), "r"(a[1]), "r"(a[2]), "r"(a[3]), "r"(b[0]), "r"(b[1]));
}
// split fp32 pair into fp16 hi pair + fp16 residual pair (packed)
__device__ __forceinline__ void cvt2h(float x, float y, uint32_t& hi, uint32_t& lo) {
    __half2 h = __floats2half2_rn(x, y);
    float rx = x - __low2float(h);
    float ry = y - __high2float(h);
    __half2 l = __floats2half2_rn(rx, ry);
    hi = *reinterpret_cast<uint32_t*>(&h);
    lo = *reinterpret_cast<uint32_t*>(&l);
}
__device__ __forceinline__ uint32_t cvth(float x, float y) {
    __half2 h = __floats2half2_rn(x, y);
    return *reinterpret_cast<uint32_t*>(&h);
}
template <int ACT>
__device__ __forceinline__ float actf(float x, int col) {
    if (ACT == 1) return fmaxf(x, 0.0f);
    if (ACT == 4) return (col < 1024) ? tanhf(x) : 1.0f / (1.0f + expf(-x));
    return x;
}

// ---------------- GEMM: C[M,N] = act(A @ fp16(B) + bias) ----------------
// A: fp16 hi plane at Ah (+ lo plane at Ah + M*K when TERMS==2). B: fp16 [K,N].
template <int ACT, int SPLIT_OUT, int TERMS>
__global__ void __launch_bounds__(256, 2)
hgemm(const __half* __restrict__ Ah,
      const __half* __restrict__ Bh,
      const float* __restrict__ bias,
      float* __restrict__ Cf, __half* __restrict__ Cs,
      int M, int N, int K, int tiles_m)
{
    extern __shared__ __align__(16) char smraw[];
    const uint32_t sb0 = smem_u32(smraw);

    const int t    = threadIdx.x;
    const int lane = t & 31;
    const int warp = t >> 5;
    const int wm   = warp >> 2;
    const int wn   = warp & 3;
    const int bm = (blockIdx.x % tiles_m) * 128;
    const int bn = (blockIdx.x / tiles_m) * 128;
    const size_t MK = (size_t)M * K;

    const int ar  = t >> 1;
    const int acH = (t & 1) * 16;
    const int br  = t >> 3;
    const int bcH = (t & 7) * 16;
    const __half* aS = Ah + (size_t)(bm + ar) * K + acH;
    const __half* bS = Bh + (size_t)br * N + bn + bcH;
    const uint32_t daB = (uint32_t)(ar * LDA + acH) * 2;
    const uint32_t dbB = (uint32_t)(br * LDB + bcH) * 2;

    float acc[4][4][4];
#pragma unroll
    for (int a = 0; a < 4; a++)
#pragma unroll
        for (int b = 0; b < 4; b++)
#pragma unroll
            for (int c = 0; c < 4; c++) acc[a][b][c] = 0.0f;

    const int nk = K / 32;

#define ISSUE(s_)                                                       \
    do {                                                                \
        const int s__ = (s_);                                           \
        if (s__ < nk) {                                                 \
            const uint32_t st = sb0 + (uint32_t)(s__ & 1) * STG;        \
            const __half* pa = aS + s__ * 32;                           \
            const uint32_t da = st + daB;                               \
            cpa16(da, pa);            cpa16(da + 16, pa + 8);           \
            if (TERMS == 2) {                                           \
                cpa16(da + APB, pa + MK);                               \
                cpa16(da + APB + 16, pa + MK + 8);                      \
            }                                                           \
            const __half* pb = bS + (size_t)(s__ * 32) * N;             \
            const uint32_t db = st + SBOF + dbB;                        \
            cpa16(db, pb);            cpa16(db + 16, pb + 8);           \
        }                                                               \
        asm volatile("cp.async.commit_group;" ::: "memory");            \
    } while (0)

    ISSUE(0); ISSUE(1);

    for (int it = 0; it < nk; ++it) {
        asm volatile("cp.async.wait_group 1;" ::: "memory");
        __syncthreads();

        const uint32_t st  = sb0 + (uint32_t)(it & 1) * STG;
        const uint32_t aHi = st;
        const uint32_t aLo = st + APB;
        const uint32_t bPl = st + SBOF;

#pragma unroll
        for (int ks = 0; ks < 2; ++ks) {
            uint32_t fB[4][2];
            const int krow  = ks * 16 + (lane & 15);
            const int nbase = wn * 32 + ((lane >> 4) << 3);
#pragma unroll
            for (int g = 0; g < 2; ++g) {
                const uint32_t off = (uint32_t)(krow * LDB + nbase + g * 16) * 2;
                uint32_t r[4];
                ldmT4(r, bPl + off);
                fB[2 * g][0] = r[0]; fB[2 * g][1] = r[1];
                fB[2 * g + 1][0] = r[2]; fB[2 * g + 1][1] = r[3];
            }
#pragma unroll
            for (int mt = 0; mt < 4; ++mt) {
                uint32_t fH[4], fL[4];
                const uint32_t aoff =
                    (uint32_t)((wm * 64 + mt * 16 + (lane & 15)) * LDA +
                               ks * 16 + ((lane >> 4) << 3)) * 2;
                ldm4(fH, aHi + aoff);
                if (TERMS == 2) ldm4(fL, aLo + aoff);
#pragma unroll
                for (int nt = 0; nt < 4; ++nt) mma_f16(acc[mt][nt], fH, fB[nt]);
                if (TERMS == 2) {
#pragma unroll
                    for (int nt = 0; nt < 4; ++nt) mma_f16(acc[mt][nt], fL, fB[nt]);
                }
            }
        }
        __syncthreads();
        ISSUE(it + 2);
    }
#undef ISSUE

    // ---- epilogue
    const int rr = lane >> 2;
    const int cc = (lane & 3) * 2;
    if (SPLIT_OUT) {
        uint32_t* Chi = (uint32_t*)Cs;
        uint32_t* Clo = (uint32_t*)(Cs + (size_t)M * N);
#pragma unroll
        for (int mt = 0; mt < 4; ++mt) {
            const int row = bm + wm * 64 + mt * 16 + rr;
#pragma unroll
            for (int nt = 0; nt < 4; ++nt) {
                const int col = bn + wn * 32 + nt * 8 + cc;
                const float b0 = __ldg(bias + col);
                const float b1 = __ldg(bias + col + 1);
                uint32_t h, l;
                cvt2h(actf<ACT>(acc[mt][nt][0] + b0, col),
                      actf<ACT>(acc[mt][nt][1] + b1, col), h, l);
                size_t ix = ((size_t)row * N + col) >> 1;
                Chi[ix] = h; Clo[ix] = l;
                cvt2h(actf<ACT>(acc[mt][nt][2] + b0, col),
                      actf<ACT>(acc[mt][nt][3] + b1, col), h, l);
                ix = ((size_t)(row + 8) * N + col) >> 1;
                Chi[ix] = h; Clo[ix] = l;
            }
        }
    } else {
#pragma unroll
        for (int mt = 0; mt < 4; ++mt) {
            const int row = bm + wm * 64 + mt * 16 + rr;
#pragma unroll
            for (int nt = 0; nt < 4; ++nt) {
                const int col = bn + wn * 32 + nt * 8 + cc;
                const float b0 = __ldg(bias + col);
                const float b1 = __ldg(bias + col + 1);
                float2 o0, o1;
                o0.x = actf<ACT>(acc[mt][nt][0] + b0, col);
                o0.y = actf<ACT>(acc[mt][nt][1] + b1, col);
                o1.x = actf<ACT>(acc[mt][nt][2] + b0, col);
                o1.y = actf<ACT>(acc[mt][nt][3] + b1, col);
                *(float2*)(Cf + (size_t)row * N + col)       = o0;
                *(float2*)(Cf + (size_t)(row + 8) * N + col) = o1;
            }
        }
    }
}

// ---------------- weight convert fp32 -> fp16 plane ----------------
__device__ __forceinline__ void conv_one(
    long long i,
    const float* w00, const float* w01, const float* w10, const float* w11,
    const float* dw0, const float* fw0, const float* iw0,
    const float* ow, __half* wbuf)
{
    const float* s; long long jsrc; long long dsti = i;
    if (i < 4194304LL)        { s = w00; jsrc = i; }
    else if (i < 12582912LL)  { s = w01; jsrc = i - 4194304; }
    else if (i < 16777216LL)  { s = w10; jsrc = i - 12582912; }
    else if (i < 25165824LL)  { s = w11; jsrc = i - 16777216; }
    else if (i < 31457280LL) {
        const long long j = i - 25165824;
        const long long r = j / 1536, c2 = j % 1536;
        const int sel = (int)(c2 / 512);
        s = sel == 0 ? dw0 : (sel == 1 ? fw0 : iw0);
        jsrc = r * 512 + (c2 - (long long)sel * 512);
    }
    else { s = ow; jsrc = i - 31457280; dsti = i + 6291456; }  // skip unused G1 slot

    const float2 v = ((const float2*)s)[jsrc];
    ((uint32_t*)wbuf)[dsti] = cvth(v.x, v.y);
}

__global__ void __launch_bounds__(256)
wconv_range(const float* w00, const float* w01, const float* w10, const float* w11,
            const float* dw0, const float* fw0, const float* iw0,
            const float* ow, __half* wbuf, long long base, long long count)
{
    const long long i = base + (long long)blockIdx.x * 256 + threadIdx.x;
    if (i >= base + count || i >= 96993280LL) return;
    conv_one(i, w00, w01, w10, w11, dw0, fw0, iw0, ow, wbuf);
}

__global__ void __launch_bounds__(256)
gbias_kernel(const float* __restrict__ db, const float* __restrict__ fb,
             const float* __restrict__ ib, float* __restrict__ out)
{
    const int c = blockIdx.x * 256 + threadIdx.x;
    if (c >= 3072) return;
    out[c] = (c < 1024) ? db[c] : (c < 2048 ? fb[c - 1024] : ib[c - 2048]);
}

// ---------------- concat [x | ctx] -> fp16 hi/lo planes ----------------
__global__ void __launch_bounds__(256)
concat_split_kernel(const float* __restrict__ x, const float* __restrict__ ctx,
                    __half* __restrict__ xcs, int first)
{
    const int gid = blockIdx.x * 256 + threadIdx.x;
    const int row = gid >> 9;
    const int c4  = gid & 511;
    float4 v;
    if (c4 < 256)   v = ((const float4*)x)[row * 256 + c4];
    else if (first) v = make_float4(0.f, 0.f, 0.f, 0.f);
    else            v = ((const float4*)ctx)[row * 256 + (c4 - 256)];
    uint32_t h0, l0, h1, l1;
    cvt2h(v.x, v.y, h0, l0);
    cvt2h(v.z, v.w, h1, l1);
    uint2* hi = (uint2*)xcs;
    uint2* lo = (uint2*)(xcs + (size_t)4096 * 2048);
    hi[gid] = make_uint2(h0, h1);
    lo[gid] = make_uint2(l0, l1);
}

// ---------------- block reduction ----------------
__device__ __forceinline__ float block_sum(float v, float* sbuf) {
    const int lane = threadIdx.x & 31;
    const int wid  = threadIdx.x >> 5;
#pragma unroll
    for (int o = 16; o; o >>= 1) v += __shfl_xor_sync(0xffffffffu, v, o);
    if (lane == 0) sbuf[wid] = v;
    __syncthreads();
    if (threadIdx.x < 32) {
        float r = (threadIdx.x < 8) ? sbuf[threadIdx.x] : 0.0f;
#pragma unroll
        for (int o = 4; o; o >>= 1) r += __shfl_xor_sync(0xffffffffu, r, o);
        if (threadIdx.x == 0) sbuf[8] = r;
    }
    __syncthreads();
    return sbuf[8];
}

__global__ void __launch_bounds__(256)
embed_ln_kernel(const int* __restrict__ ids, const float* __restrict__ table,
                const float* __restrict__ g, const float* __restrict__ b,
                float* __restrict__ out)
{
    __shared__ float sbuf[16];
    const int row = blockIdx.x;
    const int t = threadIdx.x;
    const float* e = table + (size_t)ids[row] * EDIM;
    float v[4];
    float s = 0.0f, s2 = 0.0f;
#pragma unroll
    for (int j = 0; j < 4; j++) {
        v[j] = e[t + j * 256];
        s += v[j]; s2 += v[j] * v[j];
    }
    const float S  = block_sum(s, sbuf);
    const float S2 = block_sum(s2, sbuf);
    const float mean = S * (1.0f / EDIM);
    const float var  = S2 * (1.0f / EDIM) - mean * mean;
    const float rs   = rsqrtf(var + LN_EPS);
#pragma unroll
    for (int j = 0; j < 4; j++) {
        const int c = t + j * 256;
        out[(size_t)row * EDIM + c] = (v[j] - mean) * rs * g[c] + b[c];
    }
}

// gates layout: [delta | f | i] per row of 3072
__global__ void __launch_bounds__(256)
gate_ln_kernel(const float* __restrict__ gates, float* __restrict__ ctx,
               const float* __restrict__ g, const float* __restrict__ b, int first)
{
    __shared__ float sbuf[16];
    const int row = blockIdx.x;
    const int t = threadIdx.x;
    const float* gr = gates + (size_t)row * 3072;
    float v[4];
    float s = 0.0f, s2 = 0.0f;
#pragma unroll
    for (int j = 0; j < 4; j++) {
        const int c = t + j * 256;
        const float cv = first ? 0.0f : ctx[(size_t)row * CDIM + c];
        v[j] = gr[1024 + c] * cv + gr[2048 + c] * gr[c];
        s += v[j]; s2 += v[j] * v[j];
    }
    const float S  = block_sum(s, sbuf);
    const float S2 = block_sum(s2, sbuf);
    const float mean = S * (1.0f / CDIM);
    const float var  = S2 * (1.0f / CDIM) - mean * mean;
    const float rs   = rsqrtf(var + LN_EPS);
#pragma unroll
    for (int j = 0; j < 4; j++) {
        const int c = t + j * 256;
        ctx[(size_t)row * CDIM + c] = (v[j] - mean) * rs * g[c] + b[c];
    }
}

// ---------------- host dispatch ----------------
// mode 0: trunk 2-term relu split | mode 3: trunk 1-term relu split
// mode 1: gates 1-term            | mode 2: logits 1-term
static void run_gemm(int mode, const __half* Ah, const __half* Bh,
                     const float* bias, float* Cf, __half* Cs,
                     int M, int N, int K)
{
    const int tiles_m = M / 128;
    dim3 grid(tiles_m * (N / 128)), block(256);
    if (mode == 0) {
        cudaFuncSetAttribute(hgemm<1, 1, 2>, cudaFuncAttributeMaxDynamicSharedMemorySize, GEMM_SMEM);
        hgemm<1, 1, 2><<<grid, block, GEMM_SMEM>>>(Ah, Bh, bias, Cf, Cs, M, N, K, tiles_m);
    } else if (mode == 3) {
        cudaFuncSetAttribute(hgemm<1, 1, 1>, cudaFuncAttributeMaxDynamicSharedMemorySize, GEMM_SMEM);
        hgemm<1, 1, 1><<<grid, block, GEMM_SMEM>>>(Ah, Bh, bias, Cf, Cs, M, N, K, tiles_m);
    } else if (mode == 1) {
        cudaFuncSetAttribute(hgemm<4, 0, 1>, cudaFuncAttributeMaxDynamicSharedMemorySize, GEMM_SMEM);
        hgemm<4, 0, 1><<<grid, block, GEMM_SMEM>>>(Ah, Bh, bias, Cf, Cs, M, N, K, tiles_m);
    } else {
        cudaFuncSetAttribute(hgemm<0, 0, 1>, cudaFuncAttributeMaxDynamicSharedMemorySize, GEMM_SMEM);
        hgemm<0, 0, 1><<<grid, block, GEMM_SMEM>>>(Ah, Bh, bias, Cf, Cs, M, N, K, tiles_m);
    }
}

extern "C" void kernel_launch(void* const* d_in, const int* in_sizes, int n_in,
                              void* d_out, int out_size)
{
    const int*   ids   = (const int*)d_in[0];
    const float* table = (const float*)d_in[1];
    const float* en_g  = (const float*)d_in[2];
    const float* en_b  = (const float*)d_in[3];
    const float* bA[2] = {(const float*)d_in[5],  (const float*)d_in[9]};
    const float* bB[2] = {(const float*)d_in[7],  (const float*)d_in[11]};
    const float* cg0   = (const float*)d_in[18];
    const float* cb0   = (const float*)d_in[19];
    const float* ob    = (const float*)d_in[29];
    float* out = (float*)d_out;

    __half *wbuf, *xcs, *h1s, *hs;
    float *x, *gate, *ctx, *gbias;
    cudaGetSymbolAddress((void**)&wbuf,  g_wbuf);
    cudaGetSymbolAddress((void**)&xcs,   g_xcs);
    cudaGetSymbolAddress((void**)&h1s,   g_h1s);
    cudaGetSymbolAddress((void**)&hs,    g_hs);
    cudaGetSymbolAddress((void**)&x,     g_x);
    cudaGetSymbolAddress((void**)&gate,  g_gate);
    cudaGetSymbolAddress((void**)&ctx,   g_ctx);
    cudaGetSymbolAddress((void**)&gbias, g_gbias);

    const float* W[8] = {
        (const float*)d_in[4],  (const float*)d_in[6],
        (const float*)d_in[8],  (const float*)d_in[10],
        (const float*)d_in[12], (const float*)d_in[14], (const float*)d_in[16],
        (const float*)d_in[28]};

    // 0: embed, 1: concat(blk0), 2: conv w00, 3: trunk GEMM 1 (profiled),
    // 4: conv rest, ...
    embed_ln_kernel<<<NTOK, 256>>>(ids, table, en_g, en_b, x);
    concat_split_kernel<<<(NTOK * 2048 / 4) / 256, 256>>>(x, ctx, xcs, 1);
    wconv_range<<<(4194304 + 255) / 256, 256>>>(
        W[0], W[1], W[2], W[3], W[4], W[5], W[6], W[7],
        wbuf, 0LL, 4194304LL);
    run_gemm(0, xcs, wbuf + O_W00, bA[0], nullptr, h1s, NTOK, HDIM, EDIM + CDIM);
    wconv_range<<<(int)((96993280LL - 4194304LL + 255) / 256), 256>>>(
        W[0], W[1], W[2], W[3], W[4], W[5], W[6], W[7],
        wbuf, 4194304LL, 96993280LL - 4194304LL);
    run_gemm(0, h1s, wbuf + O_W01, bB[0], nullptr, hs, NTOK, HDIM, HDIM);
    gbias_kernel<<<12, 256>>>((const float*)d_in[13], (const float*)d_in[15],
                              (const float*)d_in[17], gbias);
    run_gemm(1, hs, wbuf + O_G0, gbias, gate, nullptr, NTOK, 3072, HDIM);   // 1-term
    gate_ln_kernel<<<NTOK, 256>>>(gate, ctx, cg0, cb0, 1);

    // block 1 trunk: 1-term (low downstream amplification).
    // Block-1 gate GEMM + gate_ln remain dead code (final ctx never read).
    concat_split_kernel<<<(NTOK * 2048 / 4) / 256, 256>>>(x, ctx, xcs, 0);
    run_gemm(3, xcs, wbuf + O_W10, bA[1], nullptr, h1s, NTOK, HDIM, EDIM + CDIM);
    run_gemm(3, h1s, wbuf + O_W11, bB[1], nullptr, hs,  NTOK, HDIM, HDIM);

    // logits: 1-term fp16
    run_gemm(2, hs, wbuf + O_OW, ob, out, nullptr, NTOK, VDIM, HDIM);
}